// round 9
// baseline (speedup 1.0000x reference)
#include <cuda_runtime.h>
#include <cuda_fp16.h>

#define N_NODES   100000
#define N_EDGES   3200000
#define D_IN      128
#define D_H0      64
#define D_H1      32
#define N_GRAPHS  1024
#define N_CLASSES 16

#define SCAN_BS 1024
#define NB ((N_NODES + SCAN_BS - 1) / SCAN_BS)   // 98

// ---------------- scratch ----------------
__device__ int     g_degcnt[N_NODES];
__device__ int     g_cursor[N_NODES];
__device__ int     g_rowptr[N_NODES];
__device__ float   g_invsqrt[N_NODES];
__device__ int     g_col[N_EDGES];
__device__ __half2 g_buf0h[(size_t)N_NODES * 32];   // raw x@W0, fp16 (NOT norm-folded)
__device__ __half  g_buf1h[(size_t)N_NODES * 32];   // (h0@W1)*invsqrt, fp16
__device__ float   g_pool[N_GRAPHS * D_H1];
__device__ int     g_pcnt[N_GRAPHS];
__device__ int     g_blocktot[NB];
__device__ int     g_blockoff[NB];
__device__ int     g_scan_done;
__device__ volatile int g_scan_flag;

// ---- f32x2 packed-FMA helpers (sm_103a dual-rate fp32, PTX-only) ----
__device__ __forceinline__ unsigned long long pk2(float x, float y) {
    unsigned long long r;
    asm("mov.b64 %0, {%1, %2};" : "=l"(r) : "f"(x), "f"(y));
    return r;
}
__device__ __forceinline__ void ffma2(unsigned long long& d,
                                      unsigned long long a, unsigned long long b) {
    asm("fma.rn.f32x2 %0, %1, %2, %0;" : "+l"(d) : "l"(a), "l"(b));
}

// ---------------- init: zero everything the pipeline needs ----------------
__global__ void k_init() {
    int i = blockIdx.x * blockDim.x + threadIdx.x;
    if (i < N_NODES) g_degcnt[i] = 0;
    if (i < N_GRAPHS * D_H1) g_pool[i] = 0.f;
    if (i < N_GRAPHS) g_pcnt[i] = 0;
    if (i == 0) { g_scan_done = 0; g_scan_flag = 0; }
}

// ---------------- degree count (int4-vectorized) ----------------
__global__ void k_count(const int* __restrict__ ei) {
    int e4 = blockIdx.x * blockDim.x + threadIdx.x;
    if (e4 < N_EDGES / 4) {
        int4 r = ((const int4*)ei)[e4];
        atomicAdd(&g_degcnt[r.x], 1);
        atomicAdd(&g_degcnt[r.y], 1);
        atomicAdd(&g_degcnt[r.z], 1);
        atomicAdd(&g_degcnt[r.w], 1);
    }
}

// ---------------- fully fused scan: rowptr + cursor + invsqrt, 1 kernel ------
__global__ void k_scanF() {
    __shared__ int wsum[8];
    __shared__ int isLast;
    __shared__ int s_off;
    int t = threadIdx.x, b = blockIdx.x;
    int base = b * SCAN_BS + t * 4;
    int v[4];
#pragma unroll
    for (int k = 0; k < 4; k++) {
        int i = base + k;
        v[k] = (i < N_NODES) ? g_degcnt[i] : 0;
    }
    int tot = v[0] + v[1] + v[2] + v[3];
    int lane = t & 31, wid = t >> 5;
    int x = tot;
#pragma unroll
    for (int off = 1; off < 32; off <<= 1) {
        int y = __shfl_up_sync(0xffffffffu, x, off);
        if (lane >= off) x += y;
    }
    if (lane == 31) wsum[wid] = x;
    __syncthreads();
    if (t == 0) {
        int run = 0;
        for (int i = 0; i < 8; i++) { int tmp = wsum[i]; wsum[i] = run; run += tmp; }
        g_blocktot[b] = run;
        __threadfence();
        int d = atomicAdd(&g_scan_done, 1);
        isLast = (d == NB - 1);
    }
    __syncthreads();
    // last-arriving block scans the 98 block totals, then releases everyone
    if (isLast && t < 32) {
        int carry = 0;
        for (int bb = 0; bb < NB; bb += 32) {
            int i = bb + t;
            int vv = (i < NB) ? g_blocktot[i] : 0;
            int xx = vv;
#pragma unroll
            for (int off = 1; off < 32; off <<= 1) {
                int y = __shfl_up_sync(0xffffffffu, xx, off);
                if (t >= off) xx += y;
            }
            if (i < NB) g_blockoff[i] = xx - vv + carry;
            carry += __shfl_sync(0xffffffffu, xx, 31);
        }
        if (t == 0) { __threadfence(); g_scan_flag = 1; }
    }
    // all blocks (resident: NB=98 < 148 SMs) wait for the global offsets
    if (t == 0) {
        while (g_scan_flag == 0) __nanosleep(64);
        s_off = g_blockoff[b];
    }
    __syncthreads();
    int run = wsum[wid] + (x - tot) + s_off;
#pragma unroll
    for (int k = 0; k < 4; k++) {
        int i = base + k;
        if (i < N_NODES) {
            g_rowptr[i]  = run;
            g_cursor[i]  = run;
            g_invsqrt[i] = rsqrtf((float)(v[k] + 1));   // +1 self-loop
        }
        run += v[k];
    }
}

// ---------------- scatter edges into CSR (int4-vectorized reads) -------------
__global__ void k_scatter(const int* __restrict__ ei) {
    int e4 = blockIdx.x * blockDim.x + threadIdx.x;
    if (e4 < N_EDGES / 4) {
        int4 r = ((const int4*)ei)[e4];
        int4 c = ((const int4*)(ei + N_EDGES))[e4];
        g_col[atomicAdd(&g_cursor[r.x], 1)] = c.x;
        g_col[atomicAdd(&g_cursor[r.y], 1)] = c.y;
        g_col[atomicAdd(&g_cursor[r.z], 1)] = c.z;
        g_col[atomicAdd(&g_cursor[r.w], 1)] = c.w;
    }
}

// ---------------- GEMM0 (f32x2): buf0h = fp16(x@W0), raw — NO dependency ----
__global__ void k_gemm0(const float* __restrict__ x, const float* __restrict__ W0) {
    __shared__ float As[64][17];
    __shared__ float Bs[16][64];
    int t = threadIdx.x;
    int tx = t % 16, ty = t / 16;
    int row0 = blockIdx.x * 64;
    unsigned long long acc2[4][2];
#pragma unroll
    for (int i = 0; i < 4; i++) { acc2[i][0] = 0ull; acc2[i][1] = 0ull; }

    for (int kt = 0; kt < D_IN; kt += 16) {
        {
            int r = t >> 2, c4 = t & 3;
            int gr = row0 + r;
            float4 v = (gr < N_NODES)
                ? *(const float4*)&x[(size_t)gr * D_IN + kt + c4 * 4]
                : make_float4(0.f, 0.f, 0.f, 0.f);
            As[r][c4 * 4 + 0] = v.x; As[r][c4 * 4 + 1] = v.y;
            As[r][c4 * 4 + 2] = v.z; As[r][c4 * 4 + 3] = v.w;
        }
#pragma unroll
        for (int l = t; l < 16 * 64; l += 256) {
            int kk = l >> 6, c = l & 63;
            Bs[kk][c] = W0[(size_t)(kt + kk) * D_H0 + c];
        }
        __syncthreads();
#pragma unroll
        for (int kk = 0; kk < 16; kk++) {
            unsigned long long b0p = *(const unsigned long long*)&Bs[kk][tx * 4];
            unsigned long long b1p = *(const unsigned long long*)&Bs[kk][tx * 4 + 2];
#pragma unroll
            for (int i = 0; i < 4; i++) {
                float a = As[ty * 4 + i][kk];
                unsigned long long ap = pk2(a, a);
                ffma2(acc2[i][0], ap, b0p);
                ffma2(acc2[i][1], ap, b1p);
            }
        }
        __syncthreads();
    }
#pragma unroll
    for (int i = 0; i < 4; i++) {
        int gr = row0 + ty * 4 + i;
        if (gr < N_NODES) {
            float2 r0 = *(float2*)&acc2[i][0];
            float2 r1 = *(float2*)&acc2[i][1];
            g_buf0h[(size_t)gr * 32 + tx * 2]     = __floats2half2_rn(r0.x, r0.y);
            g_buf0h[(size_t)gr * 32 + tx * 2 + 1] = __floats2half2_rn(r1.x, r1.y);
        }
    }
}

// ---------------- agg64 (norm gathered per-edge) + fused GEMM1 ----------------
__global__ void __launch_bounds__(512) k_agg64(const float* __restrict__ b0,
                                               const float* __restrict__ W1) {
    __shared__ float W1s[64][32];
    int t = threadIdx.x;
#pragma unroll
    for (int l = t; l < 64 * 32; l += 512) W1s[l >> 5][l & 31] = W1[l];
    __syncthreads();

    int w = (blockIdx.x * blockDim.x + t) >> 5;
    int lane = t & 31;
    if (w >= N_NODES) return;
    int start = g_rowptr[w], cnt = g_degcnt[w];
    const __half2* __restrict__ G = g_buf0h;
    float accx = 0.f, accy = 0.f;
    int base = 0;
    for (; base + 32 <= cnt; base += 32) {
        int   cc  = g_col[start + base + lane];
        float isc = g_invsqrt[cc];
#pragma unroll
        for (int j0 = 0; j0 < 32; j0 += 8) {
            float2 v[8]; float ww[8];
#pragma unroll
            for (int j = 0; j < 8; j++) {
                int c = __shfl_sync(0xffffffffu, cc, j0 + j);
                ww[j] = __shfl_sync(0xffffffffu, isc, j0 + j);
                v[j]  = __half22float2(G[(size_t)c * 32 + lane]);
            }
#pragma unroll
            for (int j = 0; j < 8; j++) { accx += ww[j] * v[j].x; accy += ww[j] * v[j].y; }
        }
    }
    int rem = cnt - base;
    if (rem > 0) {
        int   cc  = (lane < rem) ? g_col[start + base + lane] : 0;
        float isc = (lane < rem) ? g_invsqrt[cc] : 0.f;
        for (int j = 0; j < rem; j++) {
            int   c  = __shfl_sync(0xffffffffu, cc, j);
            float wj = __shfl_sync(0xffffffffu, isc, j);
            float2 v = __half22float2(G[(size_t)c * 32 + lane]);
            accx += wj * v.x; accy += wj * v.y;
        }
    }
    float is = g_invsqrt[w];
    float2 s = __half22float2(G[(size_t)w * 32 + lane]);
    float h0a = fmaxf(is * (accx + is * s.x) + b0[2 * lane],     0.f);
    float h0b = fmaxf(is * (accy + is * s.y) + b0[2 * lane + 1], 0.f);

    // fused h0 @ W1 (64x32) within the warp
    float d = 0.f;
#pragma unroll
    for (int kk = 0; kk < 32; kk++) {
        float a0 = __shfl_sync(0xffffffffu, h0a, kk);
        float a1 = __shfl_sync(0xffffffffu, h0b, kk);
        d += a0 * W1s[2 * kk][lane] + a1 * W1s[2 * kk + 1][lane];
    }
    g_buf1h[(size_t)w * 32 + lane] = __float2half(d * is);
}

// ---------------- agg32 + fused mean-pool ----------------
__global__ void __launch_bounds__(512) k_agg32(const float* __restrict__ b1,
                                               const int* __restrict__ ngi) {
    int w = (blockIdx.x * blockDim.x + threadIdx.x) >> 5;
    int lane = threadIdx.x & 31;
    if (w >= N_NODES) return;
    int start = g_rowptr[w], cnt = g_degcnt[w];
    const __half* __restrict__ G = g_buf1h;
    float acc = 0.f;
    int base = 0;
    for (; base + 32 <= cnt; base += 32) {
        int cc = g_col[start + base + lane];
#pragma unroll
        for (int j0 = 0; j0 < 32; j0 += 8) {
            float v[8];
#pragma unroll
            for (int j = 0; j < 8; j++) {
                int c = __shfl_sync(0xffffffffu, cc, j0 + j);
                v[j] = __half2float(G[(size_t)c * 32 + lane]);
            }
#pragma unroll
            for (int j = 0; j < 8; j++) acc += v[j];
        }
    }
    int rem = cnt - base;
    if (rem > 0) {
        int cc = (lane < rem) ? g_col[start + base + lane] : 0;
        for (int j = 0; j < rem; j++) {
            int c = __shfl_sync(0xffffffffu, cc, j);
            acc += __half2float(G[(size_t)c * 32 + lane]);
        }
    }
    float s = __half2float(G[(size_t)w * 32 + lane]);
    float is = g_invsqrt[w];
    float o = fmaxf(is * (acc + s) + b1[lane], 0.f);
    int g = ngi[w];
    atomicAdd(&g_pool[g * D_H1 + lane], o);
    if (lane == 0) atomicAdd(&g_pcnt[g], 1);
}

// ---------------- head ----------------
__global__ void k_final(const float* __restrict__ Wd, const float* __restrict__ bd,
                        float* __restrict__ out) {
    int w = (blockIdx.x * blockDim.x + threadIdx.x) >> 5;
    int lane = threadIdx.x & 31;
    if (w >= N_GRAPHS) return;
    float v = g_pool[w * D_H1 + lane];
    float invc = 1.f / fmaxf((float)g_pcnt[w], 1.f);
    float acc = 0.f;
#pragma unroll
    for (int j = 0; j < 32; j++) {
        float pj = __shfl_sync(0xffffffffu, v, j);
        if (lane < N_CLASSES) acc += pj * Wd[j * N_CLASSES + lane];
    }
    if (lane < N_CLASSES)
        out[w * N_CLASSES + lane] = acc * invc + bd[lane];
}

// ---------------- launch: gemm0 ∥ entire CSR build ----------------
extern "C" void kernel_launch(void* const* d_in, const int* in_sizes, int n_in,
                              void* d_out, int out_size) {
    const float* x   = (const float*)d_in[0];
    const int*   ei  = (const int*)d_in[1];
    const int*   ngi = (const int*)d_in[2];
    const float* W0  = (const float*)d_in[3];
    const float* b0  = (const float*)d_in[4];
    const float* W1  = (const float*)d_in[5];
    const float* b1  = (const float*)d_in[6];
    const float* Wd  = (const float*)d_in[7];
    const float* bd  = (const float*)d_in[8];
    float* out = (float*)d_out;

    static cudaStream_t s1 = nullptr;
    static cudaEvent_t evFork = nullptr, evJoin = nullptr;
    if (!s1) {   // created once on the (non-captured) correctness call
        cudaStreamCreateWithFlags(&s1, cudaStreamNonBlocking);
        cudaEventCreateWithFlags(&evFork, cudaEventDisableTiming);
        cudaEventCreateWithFlags(&evJoin, cudaEventDisableTiming);
    }

    cudaEventRecord(evFork, 0);
    cudaStreamWaitEvent(s1, evFork, 0);
    // side stream: dense transform (no dependencies at all now)
    k_gemm0  <<<(N_NODES + 63) / 64, 256, 0, s1>>>(x, W0);
    cudaEventRecord(evJoin, s1);

    // main stream: CSR build
    k_init   <<<(N_NODES + 255) / 256, 256>>>();
    k_count  <<<(N_EDGES / 4 + 255) / 256, 256>>>(ei);
    k_scanF  <<<NB, 256>>>();
    k_scatter<<<(N_EDGES / 4 + 255) / 256, 256>>>(ei);

    cudaStreamWaitEvent(0, evJoin, 0);
    k_agg64  <<<(N_NODES * 32 + 511) / 512, 512>>>(b0, W1);
    k_agg32  <<<(N_NODES * 32 + 511) / 512, 512>>>(b1, ngi);
    k_final  <<<(N_GRAPHS * 32 + 255) / 256, 256>>>(Wd, bd, out);
}